// round 1
// baseline (speedup 1.0000x reference)
#include <cuda_runtime.h>

// Problem constants
#define B_TOK 8192
#define DIN   1024
#define HID   2048
#define DOUT  1024
#define NE    8
#define GHID  1024
#define CAP   8192   // per-expert capacity (worst case all tokens pick same expert)

#define FLAG_RELU 1
#define FLAG_ADD  2
#define FLAG_DEST 4

// ---------------- scratch (static device globals; allocation-free) ----------------
__device__ float g_hidden[(size_t)B_TOK * GHID];          //  33.5 MB gating hidden
__device__ float g_logits[(size_t)B_TOK * NE];            //  gate logits
__device__ int   g_counts[NE];                            //  per-expert row counts
__device__ int   g_tokens[(size_t)NE * CAP];              //  token index per (expert,row)
__device__ float g_wts[(size_t)NE * CAP];                 //  softmax weight per (expert,row)
__device__ int   g_dests[(size_t)NE * CAP];               //  output row = 2*token+slot
__device__ float g_h[(size_t)NE * CAP * HID];             //  536 MB  h after layer1
__device__ float g_p[(size_t)NE * CAP * HID];             //  536 MB  projection / layer2 out
__device__ float g_eout[(size_t)B_TOK * 2 * DOUT];        //  67 MB  per-slot expert output

// ---------------- tiled fp32 GEMM: out = f(A_gathered @ W + bias [+ add]) ----------------
// BM=128, BN=128, BK=16, 256 threads, 8x8 per thread.
#define BM 128
#define BN 128
#define BK 16

__global__ __launch_bounds__(256, 2) void gemm_kernel(
    const float* __restrict__ A, int aStrideE,       // A row = gather ? gather[e*CAP+r] : r + e*aStrideE; row length K
    const int*   __restrict__ gather,
    const float* __restrict__ W, long wStrideE,      // K x N row-major per expert
    const float* __restrict__ bias, int bStrideE,
    const float* __restrict__ addt,                  // capacity layout [e*CAP+r, N]
    float*       __restrict__ out, int oStrideE,     // out row = dest ? dests[...] : r + e*oStrideE; row length N
    const int*   __restrict__ counts, int Mfixed,
    int K, int N, int flags,
    const float* __restrict__ scales, const int* __restrict__ dests)
{
    const int e  = blockIdx.z;
    const int M  = counts ? counts[e] : Mfixed;
    const int m0 = blockIdx.y * BM;
    if (m0 >= M) return;                 // idle capacity tile: early exit
    const int n0 = blockIdx.x * BN;

    __shared__ float As[BK][BM];
    __shared__ float Bs[BK][BN];

    const int tid = threadIdx.x;
    const int tx  = tid & 15;
    const int ty  = tid >> 4;

    const float* We = W + (long)e * wStrideE;

    // A tile: 128 rows x 16 cols = 512 float4; 2 per thread
    const int ar0 = tid >> 2,          ak0 = (tid & 3) << 2;
    const int ar1 = (tid + 256) >> 2,  ak1 = ((tid + 256) & 3) << 2;
    const bool av0 = (m0 + ar0) < M;
    const bool av1 = (m0 + ar1) < M;
    long abase0 = 0, abase1 = 0;
    if (av0) {
        int row = gather ? gather[e * CAP + m0 + ar0] : (m0 + ar0 + e * aStrideE);
        abase0 = (long)row * K;
    }
    if (av1) {
        int row = gather ? gather[e * CAP + m0 + ar1] : (m0 + ar1 + e * aStrideE);
        abase1 = (long)row * K;
    }

    // B tile: 16 rows x 128 cols = 512 float4; 2 per thread
    const int br0 = tid >> 5,          bc0 = (tid & 31) << 2;
    const int br1 = (tid + 256) >> 5,  bc1 = ((tid + 256) & 31) << 2;

    float acc[8][8];
    #pragma unroll
    for (int i = 0; i < 8; i++)
        #pragma unroll
        for (int j = 0; j < 8; j++) acc[i][j] = 0.0f;

    for (int k0 = 0; k0 < K; k0 += BK) {
        float4 a0 = av0 ? *(const float4*)(A + abase0 + k0 + ak0) : make_float4(0,0,0,0);
        float4 a1 = av1 ? *(const float4*)(A + abase1 + k0 + ak1) : make_float4(0,0,0,0);
        float4 b0 = *(const float4*)(We + (long)(k0 + br0) * N + n0 + bc0);
        float4 b1 = *(const float4*)(We + (long)(k0 + br1) * N + n0 + bc1);

        As[ak0 + 0][ar0] = a0.x; As[ak0 + 1][ar0] = a0.y;
        As[ak0 + 2][ar0] = a0.z; As[ak0 + 3][ar0] = a0.w;
        As[ak1 + 0][ar1] = a1.x; As[ak1 + 1][ar1] = a1.y;
        As[ak1 + 2][ar1] = a1.z; As[ak1 + 3][ar1] = a1.w;
        *(float4*)&Bs[br0][bc0] = b0;
        *(float4*)&Bs[br1][bc1] = b1;
        __syncthreads();

        #pragma unroll
        for (int k = 0; k < BK; k++) {
            float am[8], bn[8];
            #pragma unroll
            for (int i = 0; i < 8; i++) am[i] = As[k][ty * 8 + i];
            #pragma unroll
            for (int j = 0; j < 8; j++) bn[j] = Bs[k][tx * 8 + j];
            #pragma unroll
            for (int i = 0; i < 8; i++)
                #pragma unroll
                for (int j = 0; j < 8; j++)
                    acc[i][j] += am[i] * bn[j];
        }
        __syncthreads();
    }

    const float* biasE = bias + (long)e * bStrideE;
    #pragma unroll
    for (int i = 0; i < 8; i++) {
        int r = m0 + ty * 8 + i;
        if (r >= M) continue;
        long addbase = (long)(e * CAP + r) * N;
        float scale = 1.0f;
        long orow;
        if (flags & FLAG_DEST) {
            scale = scales[e * CAP + r];
            orow  = dests[e * CAP + r];
        } else {
            orow = r + (long)e * oStrideE;
        }
        float* op = out + orow * N;
        #pragma unroll
        for (int j = 0; j < 8; j++) {
            int n = n0 + tx * 8 + j;
            float v = acc[i][j] + biasE[n];
            if (flags & FLAG_ADD)  v += addt[addbase + n];
            if (flags & FLAG_RELU) v = fmaxf(v, 0.0f);
            op[n] = v * scale;
        }
    }
}

// ---------------- logits: one warp per token, N=8 ----------------
__global__ __launch_bounds__(256) void logits_kernel(
    const float* __restrict__ h, const float* __restrict__ gw2,
    const float* __restrict__ gb2, float* __restrict__ logits)
{
    int warp = (blockIdx.x * blockDim.x + threadIdx.x) >> 5;
    int lane = threadIdx.x & 31;
    if (warp >= B_TOK) return;
    const float4* hrow = (const float4*)(h + (long)warp * GHID);
    float acc[NE];
    #pragma unroll
    for (int e = 0; e < NE; e++) acc[e] = 0.0f;
    for (int i = lane; i < GHID / 4; i += 32) {
        float4 hv = hrow[i];
        const float* g = gw2 + (long)(i * 4) * NE;
        #pragma unroll
        for (int e = 0; e < NE; e++)
            acc[e] += hv.x * g[e] + hv.y * g[NE + e] + hv.z * g[2 * NE + e] + hv.w * g[3 * NE + e];
    }
    #pragma unroll
    for (int e = 0; e < NE; e++)
        #pragma unroll
        for (int off = 16; off > 0; off >>= 1)
            acc[e] += __shfl_xor_sync(0xFFFFFFFFu, acc[e], off);
    if (lane == 0) {
        #pragma unroll
        for (int e = 0; e < NE; e++)
            logits[(long)warp * NE + e] = acc[e] + gb2[e];
    }
}

// ---------------- routing ----------------
__global__ void init_kernel() {
    if (threadIdx.x < NE) g_counts[threadIdx.x] = 0;
}

__global__ __launch_bounds__(256) void route_kernel() {
    int t = blockIdx.x * blockDim.x + threadIdx.x;
    if (t >= B_TOK) return;
    float v[NE];
    #pragma unroll
    for (int e = 0; e < NE; e++) v[e] = g_logits[(long)t * NE + e];
    // top-1 (earliest index wins ties, matching lax.top_k)
    int i0 = 0;
    #pragma unroll
    for (int e = 1; e < NE; e++) if (v[e] > v[i0]) i0 = e;
    // top-2
    int i1 = (i0 == 0) ? 1 : 0;
    #pragma unroll
    for (int e = 0; e < NE; e++) if (e != i0 && v[e] > v[i1]) i1 = e;
    // softmax over the two (v[i0] >= v[i1])
    float b = __expf(v[i1] - v[i0]);
    float s = 1.0f + b;
    float w0 = 1.0f / s;
    float w1 = b / s;

    int p0 = atomicAdd(&g_counts[i0], 1);
    g_tokens[i0 * CAP + p0] = t;
    g_wts[i0 * CAP + p0]    = w0;
    g_dests[i0 * CAP + p0]  = 2 * t;

    int p1 = atomicAdd(&g_counts[i1], 1);
    g_tokens[i1 * CAP + p1] = t;
    g_wts[i1 * CAP + p1]    = w1;
    g_dests[i1 * CAP + p1]  = 2 * t + 1;
}

// ---------------- final reduce: out[t] = eout[2t] + eout[2t+1] ----------------
__global__ __launch_bounds__(256) void reduce_kernel(float* __restrict__ out) {
    long idx = (long)blockIdx.x * blockDim.x + threadIdx.x;   // float4 index
    const long total = (long)B_TOK * DOUT / 4;
    if (idx >= total) return;
    long t  = idx / (DOUT / 4);
    long c4 = idx % (DOUT / 4);
    const float4* e4 = (const float4*)g_eout;
    float4 a = e4[(2 * t) * (DOUT / 4) + c4];
    float4 b = e4[(2 * t + 1) * (DOUT / 4) + c4];
    float4 r;
    r.x = a.x + b.x; r.y = a.y + b.y; r.z = a.z + b.z; r.w = a.w + b.w;
    ((float4*)out)[idx] = r;
}

// ---------------- host ----------------
extern "C" void kernel_launch(void* const* d_in, const int* in_sizes, int n_in,
                              void* d_out, int out_size) {
    const float* x   = (const float*)d_in[0];
    const float* w1  = (const float*)d_in[1];
    const float* b1  = (const float*)d_in[2];
    const float* w2  = (const float*)d_in[3];
    const float* b2  = (const float*)d_in[4];
    const float* w3  = (const float*)d_in[5];
    const float* b3  = (const float*)d_in[6];
    const float* wp  = (const float*)d_in[7];
    const float* bp  = (const float*)d_in[8];
    const float* gw1 = (const float*)d_in[9];
    const float* gb1 = (const float*)d_in[10];
    const float* gw2 = (const float*)d_in[11];
    const float* gb2 = (const float*)d_in[12];
    float* out = (float*)d_out;

    float *p_hidden, *p_logits, *p_wts, *p_h, *p_p, *p_eout;
    int   *p_counts, *p_tokens, *p_dests;
    cudaGetSymbolAddress((void**)&p_hidden, g_hidden);
    cudaGetSymbolAddress((void**)&p_logits, g_logits);
    cudaGetSymbolAddress((void**)&p_counts, g_counts);
    cudaGetSymbolAddress((void**)&p_tokens, g_tokens);
    cudaGetSymbolAddress((void**)&p_wts,    g_wts);
    cudaGetSymbolAddress((void**)&p_dests,  g_dests);
    cudaGetSymbolAddress((void**)&p_h,      g_h);
    cudaGetSymbolAddress((void**)&p_p,      g_p);
    cudaGetSymbolAddress((void**)&p_eout,   g_eout);

    // G1: gating hidden = relu(x @ gw1 + gb1)
    gemm_kernel<<<dim3(GHID / BN, B_TOK / BM, 1), 256>>>(
        x, 0, nullptr, gw1, 0, gb1, 0, nullptr,
        p_hidden, 0, nullptr, B_TOK, DIN, GHID, FLAG_RELU, nullptr, nullptr);

    // G2: logits
    logits_kernel<<<B_TOK / 8, 256>>>(p_hidden, gw2, gb2, p_logits);

    // G3: routing
    init_kernel<<<1, 32>>>();
    route_kernel<<<B_TOK / 256, 256>>>();

    // L1: h = relu(x_g @ w1 + b1)
    gemm_kernel<<<dim3(HID / BN, CAP / BM, NE), 256>>>(
        x, 0, p_tokens, w1, (long)DIN * HID, b1, HID, nullptr,
        p_h, CAP, p_counts, 0, DIN, HID, FLAG_RELU, nullptr, nullptr);

    // L2: p = x_g @ wp + bp
    gemm_kernel<<<dim3(HID / BN, CAP / BM, NE), 256>>>(
        x, 0, p_tokens, wp, (long)DIN * HID, bp, HID, nullptr,
        p_p, CAP, p_counts, 0, DIN, HID, 0, nullptr, nullptr);

    // L3: o = relu(h @ w2 + b2 + p)   (in-place into p; each element read only by its writer block)
    gemm_kernel<<<dim3(HID / BN, CAP / BM, NE), 256>>>(
        p_h, CAP, nullptr, w2, (long)HID * HID, b2, HID, p_p,
        p_p, CAP, p_counts, 0, HID, HID, FLAG_RELU | FLAG_ADD, nullptr, nullptr);

    // L4: eout[dest] = (o @ w3 + b3) * gate_w
    gemm_kernel<<<dim3(DOUT / BN, CAP / BM, NE), 256>>>(
        p_p, CAP, nullptr, w3, (long)HID * DOUT, b3, DOUT, nullptr,
        p_eout, 0, p_counts, 0, HID, DOUT, FLAG_DEST, p_wts, p_dests);

    // Final: out[t] = eout[2t] + eout[2t+1]
    long total4 = (long)B_TOK * DOUT / 4;
    reduce_kernel<<<(int)((total4 + 255) / 256), 256>>>(out);
}

// round 3
// speedup vs baseline: 1.8577x; 1.8577x over previous
#include <cuda_runtime.h>
#include <cuda_bf16.h>
#include <cstdint>

// ---------------- problem constants ----------------
#define B_TOK 8192
#define DIN   1024
#define HID   2048
#define DOUT  1024
#define NE    8
#define GHID  1024
#define CAP   8192

#define K3_IN  (3*DIN)    // 3072
#define K3_HID (3*HID)    // 6144

#define FLAG_RELU  1
#define FLAG_ADD   2
#define FLAG_SPLIT 4
#define FLAG_DEST  8
#define FLAG_OCAP  16

// ---------------- scratch (static device globals) ----------------
__device__ unsigned short g_xb  [(size_t)B_TOK*K3_IN];      // x split bf16 [hi|lo|hi]
__device__ unsigned short g_wt1 [(size_t)NE*HID*K3_IN];     // w1^T split [hi|hi|lo]
__device__ unsigned short g_wtp [(size_t)NE*HID*K3_IN];
__device__ unsigned short g_wt2 [(size_t)NE*HID*K3_HID];
__device__ unsigned short g_wt3 [(size_t)NE*DOUT*K3_HID];
__device__ unsigned short g_gwt1[(size_t)GHID*K3_IN];
__device__ unsigned short g_hs  [(size_t)NE*CAP*K3_HID];    // h split (L1 out)
__device__ unsigned short g_os  [(size_t)NE*CAP*K3_HID];    // o split (L3 out)
__device__ float g_p     [(size_t)NE*CAP*HID];              // projection (L2 out)
__device__ float g_hidden[(size_t)B_TOK*GHID];
__device__ float g_logits[(size_t)B_TOK*NE];
__device__ int   g_counts[NE];
__device__ int   g_tokens[(size_t)NE*CAP];
__device__ float g_wts   [(size_t)NE*CAP];
__device__ int   g_dests [(size_t)NE*CAP];
__device__ float g_eout  [(size_t)B_TOK*2*DOUT];

// ---------------- PTX helpers (baseline ISA only: sm_80-era features) ----------------
__device__ __forceinline__ uint32_t smem_u32(const void* p) {
    uint32_t a;
    asm("{ .reg .u64 t; cvta.to.shared.u64 t, %1; cvt.u32.u64 %0, t; }" : "=r"(a) : "l"(p));
    return a;
}
#define CPA16(dst, src) \
    asm volatile("cp.async.cg.shared.global [%0], [%1], 16;" :: "r"(dst), "l"(src) : "memory")
#define CP_COMMIT() asm volatile("cp.async.commit_group;" ::: "memory")
#define CP_WAIT1()  asm volatile("cp.async.wait_group 1;" ::: "memory")
#define LDSM4(r, addr) \
    asm volatile("ldmatrix.sync.aligned.m8n8.x4.shared.b16 {%0,%1,%2,%3}, [%4];" \
        : "=r"((r)[0]), "=r"((r)[1]), "=r"((r)[2]), "=r"((r)[3]) : "r"(addr))
#define MMA16816(d, a, b0, b1) \
    asm volatile("mma.sync.aligned.m16n8k16.row.col.f32.bf16.bf16.f32 " \
        "{%0,%1,%2,%3},{%4,%5,%6,%7},{%8,%9},{%0,%1,%2,%3};" \
        : "+f"((d)[0]), "+f"((d)[1]), "+f"((d)[2]), "+f"((d)[3]) \
        : "r"((a)[0]), "r"((a)[1]), "r"((a)[2]), "r"((a)[3]), "r"(b0), "r"(b1))

// ---------------- HMMA GEMM: tile 128x128x32, 8 warps, 3-stage cp.async ----------------
#define BM 128
#define BN 128
#define BK 32
#define ROWE 40                 // padded row stride (elements): 80B, conflict-free ldmatrix
#define ATILE_B (BM * ROWE * 2) // 10240
#define STAGE_B (2 * ATILE_B)   // 20480 (A then B)
#define STAGES 3
#define DYN_SMEM (STAGES * STAGE_B)

__global__ __launch_bounds__(256) void mma_gemm(
    const unsigned short* __restrict__ A, int aCap,
    const int* __restrict__ gather,
    const unsigned short* __restrict__ W, size_t wStrideE,
    const float* __restrict__ bias, int bStrideE,
    const float* __restrict__ addt,
    float* __restrict__ outF, unsigned short* __restrict__ outS,
    const float* __restrict__ scales, const int* __restrict__ dests,
    const int* __restrict__ counts, int Mfixed,
    int K3, int N, int flags)
{
    const int e  = blockIdx.z;
    const int M  = counts ? counts[e] : Mfixed;
    const int m0 = blockIdx.y * BM;
    if (m0 >= M) return;
    const int n0 = blockIdx.x * BN;

    extern __shared__ char smem[];
    const uint32_t sbase = smem_u32(smem);

    const int tid  = threadIdx.x;
    const int wid  = tid >> 5;
    const int lane = tid & 31;

    // ---- load mapping: thread -> one row (A and B), two 16B chunks ----
    const int lrow   = tid >> 1;           // 0..127
    const int lchunk = (tid & 1) * 2;      // chunk pair {0,1} or {2,3}
    const unsigned short* Asrc;
    {
        int r = m0 + lrow;
        int row = gather ? gather[(size_t)e * CAP + r] : (aCap ? e * CAP + r : r);
        Asrc = A + (size_t)row * K3 + lchunk * 8;
    }
    const unsigned short* Bsrc = W + (size_t)e * wStrideE + (size_t)(n0 + lrow) * K3 + lchunk * 8;
    const uint32_t a_dst = sbase + lrow * 80 + lchunk * 16;
    const uint32_t b_dst = a_dst + ATILE_B;

    // ---- fragment smem addresses ----
    const int wm = wid & 1;    // M half (64)
    const int wn = wid >> 1;   // N quarter (32)
    uint32_t aAddr[4][2], bAddr[2][2];
    {
        int arow = wm * 64 + (lane & 15);
        int acol = (lane >> 4) * 8;
        int brow = wn * 32 + ((lane >> 4) * 8) + (lane & 7);
        int bcol = ((lane >> 3) & 1) * 8;
        #pragma unroll
        for (int ks = 0; ks < 2; ks++) {
            #pragma unroll
            for (int mt = 0; mt < 4; mt++)
                aAddr[mt][ks] = sbase + ((arow + mt * 16) * ROWE + ks * 16 + acol) * 2;
            #pragma unroll
            for (int nt2 = 0; nt2 < 2; nt2++)
                bAddr[nt2][ks] = sbase + ATILE_B + ((brow + nt2 * 16) * ROWE + ks * 16 + bcol) * 2;
        }
    }

    float acc[4][4][4];
    #pragma unroll
    for (int mt = 0; mt < 4; mt++)
        #pragma unroll
        for (int nt = 0; nt < 4; nt++)
            #pragma unroll
            for (int k = 0; k < 4; k++) acc[mt][nt][k] = 0.0f;

    const int NIT = K3 / BK;

    auto load_stage = [&](int s, int it) {
        uint32_t off = s * STAGE_B;
        const unsigned short* as = Asrc + (size_t)it * BK;
        const unsigned short* bs = Bsrc + (size_t)it * BK;
        CPA16(a_dst + off,      as);
        CPA16(a_dst + off + 16, as + 8);
        CPA16(b_dst + off,      bs);
        CPA16(b_dst + off + 16, bs + 8);
    };

    load_stage(0, 0); CP_COMMIT();
    load_stage(1, 1); CP_COMMIT();

    for (int it = 0; it < NIT; it++) {
        CP_WAIT1();
        __syncthreads();
        if (it + STAGES - 1 < NIT) load_stage((it + STAGES - 1) % STAGES, it + STAGES - 1);
        CP_COMMIT();

        const uint32_t soff = (it % STAGES) * STAGE_B;
        #pragma unroll
        for (int ks = 0; ks < 2; ks++) {
            uint32_t af[4][4], bf[2][4];
            #pragma unroll
            for (int mt = 0; mt < 4; mt++) LDSM4(af[mt], aAddr[mt][ks] + soff);
            #pragma unroll
            for (int nt2 = 0; nt2 < 2; nt2++) LDSM4(bf[nt2], bAddr[nt2][ks] + soff);
            #pragma unroll
            for (int mt = 0; mt < 4; mt++)
                #pragma unroll
                for (int nt = 0; nt < 4; nt++)
                    MMA16816(acc[mt][nt], af[mt], bf[nt >> 1][(nt & 1) * 2], bf[nt >> 1][(nt & 1) * 2 + 1]);
        }
    }

    // ---- epilogue: direct from c-fragments ----
    const float* biasE = bias + (size_t)e * bStrideE;
    const int cq = (lane & 3) * 2;
    const int r0 = lane >> 2;
    float b2v[4][2];
    #pragma unroll
    for (int nt = 0; nt < 4; nt++) {
        int n = n0 + wn * 32 + nt * 8 + cq;
        b2v[nt][0] = biasE[n];
        b2v[nt][1] = biasE[n + 1];
    }

    #pragma unroll
    for (int mt = 0; mt < 4; mt++) {
        #pragma unroll
        for (int h = 0; h < 2; h++) {
            int row = m0 + wm * 64 + mt * 16 + r0 + h * 8;
            if (row >= M) continue;
            size_t erow = (size_t)e * CAP + row;
            float  sc = 1.0f;
            size_t orow = 0;
            if (flags & FLAG_DEST) {
                sc   = scales[erow];
                orow = (size_t)dests[erow];
            } else if (flags & FLAG_OCAP) {
                orow = erow;
            } else {
                orow = (size_t)row;
            }
            #pragma unroll
            for (int nt = 0; nt < 4; nt++) {
                int n = n0 + wn * 32 + nt * 8 + cq;
                float v0 = acc[mt][nt][h * 2]     + b2v[nt][0];
                float v1 = acc[mt][nt][h * 2 + 1] + b2v[nt][1];
                if (flags & FLAG_ADD) {
                    float2 ad = *(const float2*)(addt + erow * N + n);
                    v0 += ad.x; v1 += ad.y;
                }
                if (flags & FLAG_RELU) { v0 = fmaxf(v0, 0.0f); v1 = fmaxf(v1, 0.0f); }
                if (flags & FLAG_SPLIT) {
                    __nv_bfloat16 h0 = __float2bfloat16(v0);
                    __nv_bfloat16 h1 = __float2bfloat16(v1);
                    __nv_bfloat16 l0 = __float2bfloat16(v0 - __bfloat162float(h0));
                    __nv_bfloat16 l1 = __float2bfloat16(v1 - __bfloat162float(h1));
                    size_t ob = erow * (size_t)(3 * N);
                    __nv_bfloat162* os = (__nv_bfloat162*)outS;
                    *(__nv_bfloat162*)(outS + ob + n)         = __nv_bfloat162(h0, h1);
                    *(__nv_bfloat162*)(outS + ob + N + n)     = __nv_bfloat162(l0, l1);
                    *(__nv_bfloat162*)(outS + ob + 2 * N + n) = __nv_bfloat162(h0, h1);
                    (void)os;
                } else {
                    float2 o2; o2.x = v0 * sc; o2.y = v1 * sc;
                    *(float2*)(outF + orow * N + n) = o2;
                }
            }
        }
    }
}

// ---------------- conversion kernels ----------------
// x [B,K] fp32 -> xb [B,3K] bf16: [hi | lo | hi]
__global__ __launch_bounds__(256) void convert_x(const float* __restrict__ x,
                                                 unsigned short* __restrict__ xb,
                                                 int K, size_t total)
{
    size_t idx = (size_t)blockIdx.x * blockDim.x + threadIdx.x;
    if (idx >= total) return;
    size_t m = idx / K;
    int    k = (int)(idx % K);
    float v = x[idx];
    __nv_bfloat16 hi = __float2bfloat16(v);
    __nv_bfloat16 lo = __float2bfloat16(v - __bfloat162float(hi));
    __nv_bfloat16* o = (__nv_bfloat16*)(xb + m * (size_t)(3 * K));
    o[k]         = hi;
    o[K + k]     = lo;
    o[2 * K + k] = hi;
}

// W [E,K,N] fp32 -> Wt [E,N,3K] bf16: [hi | hi | lo]  (transposed)
__global__ __launch_bounds__(256) void convert_w(const float* __restrict__ W,
                                                 unsigned short* __restrict__ Wt,
                                                 int K, int N)
{
    const int e = blockIdx.z;
    __shared__ float t[32][33];
    const int n0 = blockIdx.x * 32;
    const int k0 = blockIdx.y * 32;
    const float* We = W + (size_t)e * K * N;
    #pragma unroll
    for (int j = 0; j < 4; j++) {
        int k = k0 + threadIdx.y + j * 8;
        t[threadIdx.y + j * 8][threadIdx.x] = We[(size_t)k * N + n0 + threadIdx.x];
    }
    __syncthreads();
    unsigned short* Wte = Wt + (size_t)e * N * (size_t)(3 * K);
    #pragma unroll
    for (int j = 0; j < 4; j++) {
        int n = n0 + threadIdx.y + j * 8;
        int k = k0 + threadIdx.x;
        float v = t[threadIdx.x][threadIdx.y + j * 8];
        __nv_bfloat16 hi = __float2bfloat16(v);
        __nv_bfloat16 lo = __float2bfloat16(v - __bfloat162float(hi));
        __nv_bfloat16* o = (__nv_bfloat16*)(Wte + (size_t)n * (size_t)(3 * K));
        o[k]         = hi;
        o[K + k]     = hi;
        o[2 * K + k] = lo;
    }
}

// ---------------- gating logits: one warp per token, N=8 ----------------
__global__ __launch_bounds__(256) void logits_kernel(
    const float* __restrict__ h, const float* __restrict__ gw2,
    const float* __restrict__ gb2, float* __restrict__ logits)
{
    int warp = (blockIdx.x * blockDim.x + threadIdx.x) >> 5;
    int lane = threadIdx.x & 31;
    if (warp >= B_TOK) return;
    const float4* hrow = (const float4*)(h + (size_t)warp * GHID);
    float acc[NE];
    #pragma unroll
    for (int e = 0; e < NE; e++) acc[e] = 0.0f;
    for (int i = lane; i < GHID / 4; i += 32) {
        float4 hv = hrow[i];
        const float* g = gw2 + (size_t)(i * 4) * NE;
        #pragma unroll
        for (int e = 0; e < NE; e++)
            acc[e] += hv.x * g[e] + hv.y * g[NE + e] + hv.z * g[2 * NE + e] + hv.w * g[3 * NE + e];
    }
    #pragma unroll
    for (int e = 0; e < NE; e++)
        #pragma unroll
        for (int off = 16; off > 0; off >>= 1)
            acc[e] += __shfl_xor_sync(0xFFFFFFFFu, acc[e], off);
    if (lane == 0) {
        #pragma unroll
        for (int e = 0; e < NE; e++)
            logits[(size_t)warp * NE + e] = acc[e] + gb2[e];
    }
}

// ---------------- routing ----------------
__global__ void init_kernel() {
    if (threadIdx.x < NE) g_counts[threadIdx.x] = 0;
}

__global__ __launch_bounds__(256) void route_kernel() {
    int t = blockIdx.x * blockDim.x + threadIdx.x;
    if (t >= B_TOK) return;
    float v[NE];
    #pragma unroll
    for (int e = 0; e < NE; e++) v[e] = g_logits[(size_t)t * NE + e];
    int i0 = 0;
    #pragma unroll
    for (int e = 1; e < NE; e++) if (v[e] > v[i0]) i0 = e;
    int i1 = (i0 == 0) ? 1 : 0;
    #pragma unroll
    for (int e = 0; e < NE; e++) if (e != i0 && v[e] > v[i1]) i1 = e;
    float b = __expf(v[i1] - v[i0]);
    float s = 1.0f + b;
    float w0 = 1.0f / s;
    float w1 = b / s;

    int p0 = atomicAdd(&g_counts[i0], 1);
    g_tokens[i0 * CAP + p0] = t;
    g_wts[i0 * CAP + p0]    = w0;
    g_dests[i0 * CAP + p0]  = 2 * t;

    int p1 = atomicAdd(&g_counts[i1], 1);
    g_tokens[i1 * CAP + p1] = t;
    g_wts[i1 * CAP + p1]    = w1;
    g_dests[i1 * CAP + p1]  = 2 * t + 1;
}

// ---------------- final reduce ----------------
__global__ __launch_bounds__(256) void reduce_kernel(float* __restrict__ out) {
    size_t idx = (size_t)blockIdx.x * blockDim.x + threadIdx.x;
    const size_t total = (size_t)B_TOK * DOUT / 4;
    if (idx >= total) return;
    size_t t  = idx / (DOUT / 4);
    size_t c4 = idx % (DOUT / 4);
    const float4* e4 = (const float4*)g_eout;
    float4 a = e4[(2 * t) * (DOUT / 4) + c4];
    float4 b = e4[(2 * t + 1) * (DOUT / 4) + c4];
    float4 r;
    r.x = a.x + b.x; r.y = a.y + b.y; r.z = a.z + b.z; r.w = a.w + b.w;
    ((float4*)out)[idx] = r;
}

// ---------------- host ----------------
extern "C" void kernel_launch(void* const* d_in, const int* in_sizes, int n_in,
                              void* d_out, int out_size) {
    const float* x   = (const float*)d_in[0];
    const float* w1  = (const float*)d_in[1];
    const float* b1  = (const float*)d_in[2];
    const float* w2  = (const float*)d_in[3];
    const float* b2  = (const float*)d_in[4];
    const float* w3  = (const float*)d_in[5];
    const float* b3  = (const float*)d_in[6];
    const float* wp  = (const float*)d_in[7];
    const float* bp  = (const float*)d_in[8];
    const float* gw1 = (const float*)d_in[9];
    const float* gb1 = (const float*)d_in[10];
    const float* gw2 = (const float*)d_in[11];
    const float* gb2 = (const float*)d_in[12];
    float* out = (float*)d_out;

    unsigned short *p_xb, *p_wt1, *p_wtp, *p_wt2, *p_wt3, *p_gwt1, *p_hs, *p_os;
    float *p_p, *p_hidden, *p_logits, *p_wts, *p_eout;
    int *p_counts, *p_tokens, *p_dests;
    cudaGetSymbolAddress((void**)&p_xb,     g_xb);
    cudaGetSymbolAddress((void**)&p_wt1,    g_wt1);
    cudaGetSymbolAddress((void**)&p_wtp,    g_wtp);
    cudaGetSymbolAddress((void**)&p_wt2,    g_wt2);
    cudaGetSymbolAddress((void**)&p_wt3,    g_wt3);
    cudaGetSymbolAddress((void**)&p_gwt1,   g_gwt1);
    cudaGetSymbolAddress((void**)&p_hs,     g_hs);
    cudaGetSymbolAddress((void**)&p_os,     g_os);
    cudaGetSymbolAddress((void**)&p_p,      g_p);
    cudaGetSymbolAddress((void**)&p_hidden, g_hidden);
    cudaGetSymbolAddress((void**)&p_logits, g_logits);
    cudaGetSymbolAddress((void**)&p_wts,    g_wts);
    cudaGetSymbolAddress((void**)&p_eout,   g_eout);
    cudaGetSymbolAddress((void**)&p_counts, g_counts);
    cudaGetSymbolAddress((void**)&p_tokens, g_tokens);
    cudaGetSymbolAddress((void**)&p_dests,  g_dests);

    cudaFuncSetAttribute(mma_gemm, cudaFuncAttributeMaxDynamicSharedMemorySize, DYN_SMEM);

    // conversions
    {
        size_t total = (size_t)B_TOK * DIN;
        convert_x<<<(unsigned)((total + 255) / 256), 256>>>(x, p_xb, DIN, total);
    }
    convert_w<<<dim3(HID / 32, DIN / 32, NE),  dim3(32, 8)>>>(w1,  p_wt1,  DIN, HID);
    convert_w<<<dim3(HID / 32, DIN / 32, NE),  dim3(32, 8)>>>(wp,  p_wtp,  DIN, HID);
    convert_w<<<dim3(HID / 32, HID / 32, NE),  dim3(32, 8)>>>(w2,  p_wt2,  HID, HID);
    convert_w<<<dim3(DOUT / 32, HID / 32, NE), dim3(32, 8)>>>(w3,  p_wt3,  HID, DOUT);
    convert_w<<<dim3(GHID / 32, DIN / 32, 1),  dim3(32, 8)>>>(gw1, p_gwt1, DIN, GHID);

    // G1: gating hidden = relu(x @ gw1 + gb1)
    mma_gemm<<<dim3(GHID / BN, B_TOK / BM, 1), 256, DYN_SMEM>>>(
        p_xb, 0, nullptr, p_gwt1, 0, gb1, 0, nullptr,
        p_hidden, nullptr, nullptr, nullptr, nullptr, B_TOK, K3_IN, GHID, FLAG_RELU);

    // G2 + routing
    logits_kernel<<<B_TOK / 8, 256>>>(p_hidden, gw2, gb2, p_logits);
    init_kernel<<<1, 32>>>();
    route_kernel<<<B_TOK / 256, 256>>>();

    // L1: h = relu(x_g @ w1 + b1) -> split bf16
    mma_gemm<<<dim3(HID / BN, CAP / BM, NE), 256, DYN_SMEM>>>(
        p_xb, 0, p_tokens, p_wt1, (size_t)HID * K3_IN, b1, HID, nullptr,
        nullptr, p_hs, nullptr, nullptr, p_counts, 0, K3_IN, HID, FLAG_RELU | FLAG_SPLIT);

    // L2: p = x_g @ wp + bp  (fp32, capacity layout)
    mma_gemm<<<dim3(HID / BN, CAP / BM, NE), 256, DYN_SMEM>>>(
        p_xb, 0, p_tokens, p_wtp, (size_t)HID * K3_IN, bp, HID, nullptr,
        p_p, nullptr, nullptr, nullptr, p_counts, 0, K3_IN, HID, FLAG_OCAP);

    // L3: o = relu(h @ w2 + b2 + p) -> split bf16
    mma_gemm<<<dim3(HID / BN, CAP / BM, NE), 256, DYN_SMEM>>>(
        p_hs, 1, nullptr, p_wt2, (size_t)HID * K3_HID, b2, HID, p_p,
        nullptr, p_os, nullptr, nullptr, p_counts, 0, K3_HID, HID,
        FLAG_RELU | FLAG_ADD | FLAG_SPLIT);

    // L4: eout[dest] = (o @ w3 + b3) * gate_w
    mma_gemm<<<dim3(DOUT / BN, CAP / BM, NE), 256, DYN_SMEM>>>(
        p_os, 1, nullptr, p_wt3, (size_t)DOUT * K3_HID, b3, DOUT, nullptr,
        p_eout, nullptr, p_wts, p_dests, p_counts, 0, K3_HID, DOUT, FLAG_DEST);

    // reduce
    size_t total4 = (size_t)B_TOK * DOUT / 4;
    reduce_kernel<<<(unsigned)((total4 + 255) / 256), 256>>>(out);
}